// round 13
// baseline (speedup 1.0000x reference)
#include <cuda_runtime.h>
#include <math.h>

#define Bn 16
#define Nn 25000
#define Mn 64
#define TILE 256
#define NTILES ((Nn + TILE - 1) / TILE)   // 98

// ---- scratch (no allocations allowed; zero-initialized at load) ----
// g_pack maintained by atomicMax (idempotent across replays), reset by k_final.
__device__ unsigned long long g_pack[Bn*Mn];   // (iou_bits<<32) | ~idx
__device__ float g_focal[Bn];

// One 256-pred tile per block. Lane l of each warp owns targets l and l+32.
// Each iteration streams TWO preds (k, k+16) of this warp's 32-pred stripe ->
// 4 independent IoU chains per lane for latency hiding. Argmax tracked by
// packing the 5-bit pred slot into the cleared low mantissa bits + FMAX.
// launch_bounds(256,6): force regs<=42 so 6 blocks/SM fit (occ 62.5->75%).
__global__ __launch_bounds__(256, 6) void k_main(const float* __restrict__ preds,
                                                 const float* __restrict__ targets,
                                                 float* __restrict__ out) {
    const int b    = blockIdx.y;
    const int base = blockIdx.x * TILE;
    const int tid  = threadIdx.x;
    const int lane = tid & 31;
    const int warp = tid >> 5;

    __shared__ float4 s_box[TILE];
    __shared__ float  s_area[TILE];
    __shared__ unsigned long long s_m[8*Mn];
    __shared__ float  s_red[8];

    // zero the output for k_final's atomicAdd (stream order makes this safe)
    if (b == 0 && blockIdx.x == 0 && tid == 96) out[0] = 0.f;

    const float4 t0 = __ldg((const float4*)targets + (b*Mn + lane));
    const float4 t1 = __ldg((const float4*)targets + (b*Mn + lane + 32));
    const float ta0 = (t0.z - t0.x) * (t0.w - t0.y);
    const float ta1 = (t1.z - t1.x) * (t1.w - t1.y);

    const int cnt = min(TILE, Nn - base);
    float facc = 0.f;
    {
        // stage + convert + focal(target=0), fast-math (budget 1e-3, err ~1e-6)
        float x1, y1, x2, y2, area;
        if (tid < cnt) {
            const float* pr = preds + ((size_t)b * Nn + base + tid) * 5;
            float cx = pr[0], cy = pr[1];
            float w = fmaxf(pr[2], 1e-4f), h = fmaxf(pr[3], 1e-4f);
            float conf = pr[4];
            x1 = cx - 0.5f * w; x2 = cx + 0.5f * w;
            y1 = cy - 0.5f * h; y2 = cy + 0.5f * h;
            area = (x2 - x1) * (y2 - y1);
            // focal(target=0): 0.75 * clamp(sigmoid)^2 * softplus(conf)
            float en  = __expf(-fabsf(conf));           // e^{-|c|} in (0,1]
            float ce  = fmaxf(conf, 0.f) + __logf(1.f + en);
            float rp  = __fdividef(1.f, 1.f + en);
            float p   = (conf >= 0.f) ? rp : 1.f - rp;  // sigmoid(conf)
            float om  = fminf(fmaxf(p, 1e-6f), 1.f - 1e-6f);
            facc = 0.75f * om * om * ce;
        } else {
            // pad: degenerate far box -> iou exactly 0; loses all real ties
            x1 = y1 = x2 = y2 = -3e8f; area = 0.f;
        }
        s_box[tid]  = make_float4(x1, y1, x2, y2);
        s_area[tid] = area;
    }
    __syncthreads();

    // best = float whose bits are ((iou_bits & ~31) | slot); iou >= 0 so FMAX
    // ordering == unsigned ordering. Masking costs <=31 ulp (~4e-6 rel) noise.
    float best0 = 0.f, best1 = 0.f;
    const int pbase = base + warp * 32;

    #pragma unroll
    for (int k = 0; k < 16; k++) {
        const float4 bxA = s_box[warp * 32 + k];        // broadcast LDS
        const float  arA = s_area[warp * 32 + k];
        const float4 bxB = s_box[warp * 32 + k + 16];
        const float  arB = s_area[warp * 32 + k + 16];

        // chain A0
        {
            float iw = fmaxf(fminf(bxA.z, t0.z) - fmaxf(bxA.x, t0.x), 0.f);
            float ih = fmaxf(fminf(bxA.w, t0.w) - fmaxf(bxA.y, t0.y), 0.f);
            float inter = iw * ih;
            float iou = __fdividef(inter, arA + ta0 - inter);
            unsigned cb = (__float_as_uint(iou) & ~31u) | (unsigned)k;
            best0 = fmaxf(best0, __uint_as_float(cb));
        }
        // chain B0
        {
            float iw = fmaxf(fminf(bxB.z, t0.z) - fmaxf(bxB.x, t0.x), 0.f);
            float ih = fmaxf(fminf(bxB.w, t0.w) - fmaxf(bxB.y, t0.y), 0.f);
            float inter = iw * ih;
            float iou = __fdividef(inter, arB + ta0 - inter);
            unsigned cb = (__float_as_uint(iou) & ~31u) | (unsigned)(k + 16);
            best0 = fmaxf(best0, __uint_as_float(cb));
        }
        // chain A1
        {
            float iw = fmaxf(fminf(bxA.z, t1.z) - fmaxf(bxA.x, t1.x), 0.f);
            float ih = fmaxf(fminf(bxA.w, t1.w) - fmaxf(bxA.y, t1.y), 0.f);
            float inter = iw * ih;
            float iou = __fdividef(inter, arA + ta1 - inter);
            unsigned cb = (__float_as_uint(iou) & ~31u) | (unsigned)k;
            best1 = fmaxf(best1, __uint_as_float(cb));
        }
        // chain B1
        {
            float iw = fmaxf(fminf(bxB.z, t1.z) - fmaxf(bxB.x, t1.x), 0.f);
            float ih = fmaxf(fminf(bxB.w, t1.w) - fmaxf(bxB.y, t1.y), 0.f);
            float inter = iw * ih;
            float iou = __fdividef(inter, arB + ta1 - inter);
            unsigned cb = (__float_as_uint(iou) & ~31u) | (unsigned)(k + 16);
            best1 = fmaxf(best1, __uint_as_float(cb));
        }
    }

    // decode slot from the low 5 bits; keep the (masked) iou bits as the value
    const unsigned ub0 = __float_as_uint(best0);
    const unsigned ub1 = __float_as_uint(best1);
    const int bi0 = pbase + (int)(ub0 & 31u);
    const int bi1 = pbase + (int)(ub1 & 31u);

    // pack: higher iou wins; on exact tie, ~idx makes SMALLER idx win
    s_m[warp*Mn + lane]      = ((unsigned long long)ub0 << 32) | (unsigned)(~bi0);
    s_m[warp*Mn + lane + 32] = ((unsigned long long)ub1 << 32) | (unsigned)(~bi1);

    // focal warp-reduce
    #pragma unroll
    for (int off = 16; off; off >>= 1)
        facc += __shfl_xor_sync(0xffffffffu, facc, off);
    if (lane == 0) s_red[warp] = facc;
    __syncthreads();

    if (tid < Mn) {
        unsigned long long bv = 0ull;
        #pragma unroll
        for (int w = 0; w < 8; w++) {
            unsigned long long v = s_m[w*Mn + tid];
            bv = (v > bv) ? v : bv;
        }
        atomicMax(&g_pack[b*Mn + tid], bv);
    }
    if (tid == 64) {
        float s = 0.f;
        #pragma unroll
        for (int w = 0; w < 8; w++) s += s_red[w];
        atomicAdd(&g_focal[b], s);
    }
}

// Latency-lean tail: one image per block (16 x 64). All loads prefetched
// before the dedup; unconditional compute with masked accumulate; fast-math
// intrinsics; shuffle reductions.  (UNCHANGED — validated R8/R10/R11)
__global__ __launch_bounds__(64) void k_final(const float* __restrict__ preds,
                                              const float* __restrict__ targets,
                                              float* __restrict__ out) {
    const int b    = blockIdx.x;
    const int m    = threadIdx.x;
    const int lane = m & 31;
    const int w    = m >> 5;

    __shared__ float s_iou[Mn];
    __shared__ int   s_idx[Mn];
    __shared__ float s_c[2], s_f[2];
    __shared__ int   s_n[2];

    // --- independent prefetches (issue ASAP) ---
    const float gf = g_focal[b];                         // broadcast load
    unsigned long long v = g_pack[b*Mn + m];
    g_pack[b*Mn + m] = 0ull;                             // reset for next replay
    const float iou_b = __uint_as_float((unsigned)(v >> 32));
    int idx = (int)(~(unsigned)v);
    idx = min(max(idx, 0), Nn - 1);                      // pad-safe clamp

    // prefetch the matched pred (overlaps the dedup below)
    const float* pr = preds + ((size_t)b*Nn + idx) * 5;
    const float cx = pr[0], cy = pr[1];
    const float pw = fmaxf(pr[2], 1e-4f), ph = fmaxf(pr[3], 1e-4f);
    const float conf = pr[4];
    const float4 t = __ldg((const float4*)targets + (b*Mn + m));

    s_iou[m] = iou_b;
    s_idx[m] = idx;
    __syncthreads();

    // greedy dedup, closed form
    bool ok = iou_b > 0.2f;
    for (int mp = 0; mp < m; mp++)
        ok = ok && !(s_idx[mp] == idx && s_iou[mp] > 0.2f);

    // --- unconditional CIoU + focal correction, masked at accumulate ---
    const float x1p = cx - 0.5f*pw, x2p = cx + 0.5f*pw;
    const float y1p = cy - 0.5f*ph, y2p = cy + 0.5f*ph;
    const float x1t = t.x, y1t = t.y, x2t = t.z, y2t = t.w;

    float inter = fmaxf(fminf(x2p,x2t) - fmaxf(x1p,x1t), 0.f)
                * fmaxf(fminf(y2p,y2t) - fmaxf(y1p,y1t), 0.f);
    float un  = (x2p-x1p)*(y2p-y1p) + (x2t-x1t)*(y2t-y1t) - inter;
    float iou = __fdividef(inter, un + 1e-7f);
    float cw = fmaxf(x2p,x2t) - fminf(x1p,x1t);
    float ch = fmaxf(y2p,y2t) - fminf(y1p,y1t);
    float diag = cw*cw + ch*ch + 1e-7f;
    float dx = x1p + x2p - x1t - x2t;
    float dy = y1p + y2p - y1t - y2t;
    float centers = (dx*dx + dy*dy) * 0.25f;
    float wp = x2p - x1p, hp = y2p - y1p;
    float wt = x2t - x1t, ht = y2t - y1t;
    float dv = atanf(__fdividef(wt, ht)) - atanf(__fdividef(wp, hp));
    float vv = (float)(4.0/(M_PI*M_PI)) * dv * dv;
    float alpha = __fdividef(vv, 1.f - iou + vv + 1e-7f);
    float ci = 1.f - iou + __fdividef(centers, diag) + alpha*vv;

    // focal(target=1) - focal(target=0) correction
    float pp  = __fdividef(1.f, 1.f + __expf(-conf));
    float l1e = __logf(1.f + __expf(-fabsf(conf)));
    float ce1 = fmaxf(conf, 0.f) - conf + l1e;
    float ce0 = fmaxf(conf, 0.f) + l1e;
    float pt1 = fminf(fmaxf(pp,       1e-6f), 1.f - 1e-6f);
    float pt0 = fminf(fmaxf(1.f - pp, 1e-6f), 1.f - 1e-6f);
    float a1 = 1.f - pt1, a0 = 1.f - pt0;
    float fd = 0.25f*a1*a1*ce1 - 0.75f*a0*a0*ce0;

    const float msk = ok ? 1.f : 0.f;
    ci *= msk; fd *= msk;
    int n = ok ? 1 : 0;

    // two-warp shuffle reduction
    #pragma unroll
    for (int off = 16; off; off >>= 1) {
        ci += __shfl_xor_sync(0xffffffffu, ci, off);
        fd += __shfl_xor_sync(0xffffffffu, fd, off);
        n  += __shfl_xor_sync(0xffffffffu, n,  off);
    }
    if (lane == 0) { s_c[w] = ci; s_f[w] = fd; s_n[w] = n; }
    __syncthreads();

    if (m == 0) {
        float sc = s_c[0] + s_c[1];
        float sf = s_f[0] + s_f[1];
        int   nn = s_n[0] + s_n[1];
        float conf_loss = (gf + sf) * (1.f / (float)Nn);
        g_focal[b] = 0.f;                  // reset for next replay
        float box = (nn > 0) ? __fdividef(sc, (float)nn) : 0.f;
        atomicAdd(out, (conf_loss + box) * (1.f / (float)Bn));
    }
}

extern "C" void kernel_launch(void* const* d_in, const int* in_sizes, int n_in,
                              void* d_out, int out_size) {
    const float* preds   = (const float*)d_in[0];
    const float* targets = (const float*)d_in[1];
    float* out = (float*)d_out;

    k_main <<<dim3(NTILES, Bn), 256>>>(preds, targets, out);
    k_final<<<Bn, Mn>>>(preds, targets, out);
}